// round 16
// baseline (speedup 1.0000x reference)
#include <cuda_runtime.h>
#include <cuda_fp16.h>

#define Bq 8
#define Sq 1024
#define Dm 1024
#define NH 16
#define DH 64

#define TS  72     // half tile row stride (144B: +4 banks/row)
#define SCL 0.18033688011112043f  // 0.125 * log2(e), folded into Q at qkv store

// ---- scratch (device globals: allocation-free rule) ----
__device__ __half g_Hh[(size_t)Bq*Sq*Dm];
__device__ __half g_Q[(size_t)Bq*NH*Sq*DH];
__device__ __half g_K[(size_t)Bq*NH*Sq*DH];
__device__ __half g_V[(size_t)Bq*NH*Sq*DH];
__device__ __half g_heads[(size_t)Bq*Sq*Dm];
__device__ __half g_Woh[(size_t)Dm*Dm];
__device__ unsigned g_mb[(size_t)Bq*Sq*32];   // bit-packed mask

// ---- helpers ----
__device__ __forceinline__ void mma_f16(float c[4], const unsigned a[4],
                                        unsigned b0, unsigned b1) {
    asm volatile(
        "mma.sync.aligned.m16n8k16.row.col.f32.f16.f16.f32 "
        "{%0,%1,%2,%3}, {%4,%5,%6,%7}, {%8,%9}, {%0,%1,%2,%3};"
        : "+f"(c[0]), "+f"(c[1]), "+f"(c[2]), "+f"(c[3])
        : "r"(a[0]), "r"(a[1]), "r"(a[2]), "r"(a[3]), "r"(b0), "r"(b1));
}
__device__ __forceinline__ unsigned sptr(const void* p) {
    return (unsigned)__cvta_generic_to_shared(p);
}
__device__ __forceinline__ void ldm_x4(unsigned r[4], unsigned addr) {
    asm volatile("ldmatrix.sync.aligned.m8n8.x4.shared.b16 {%0,%1,%2,%3}, [%4];"
                 : "=r"(r[0]), "=r"(r[1]), "=r"(r[2]), "=r"(r[3]) : "r"(addr));
}
__device__ __forceinline__ void ldm_x4_t(unsigned r[4], unsigned addr) {
    asm volatile("ldmatrix.sync.aligned.m8n8.x4.trans.shared.b16 {%0,%1,%2,%3}, [%4];"
                 : "=r"(r[0]), "=r"(r[1]), "=r"(r[2]), "=r"(r[3]) : "r"(addr));
}
__device__ __forceinline__ void cpa16(unsigned dst, const void* src) {
    asm volatile("cp.async.cg.shared.global [%0], [%1], 16;" :: "r"(dst), "l"(src));
}
#define CPA_COMMIT() asm volatile("cp.async.commit_group;")
#define CPA_WAIT(n)  asm volatile("cp.async.wait_group %0;" :: "n"(n))
__device__ __forceinline__ float ex2f(float x) {
    float y;
    asm("ex2.approx.f32 %0, %1;" : "=f"(y) : "f"(x));
    return y;
}

// ============================================================================
// K0a: Wo f32 -> half.  K0b: H f32 -> half.  K0c: mask -> bitpack.
// ============================================================================
__global__ void wconv_kernel(const float* __restrict__ Wo) {
    int i = (blockIdx.x * 256 + threadIdx.x) * 4;
    float4 v = *(const float4*)&Wo[i];
    __half2* dst = (__half2*)&g_Woh[i];
    dst[0] = __floats2half2_rn(v.x, v.y);
    dst[1] = __floats2half2_rn(v.z, v.w);
}
__global__ void hconv_kernel(const float* __restrict__ H) {
    int i = (blockIdx.x * 256 + threadIdx.x) * 4;
    float4 v = *(const float4*)&H[i];
    __half2* dst = (__half2*)&g_Hh[i];
    dst[0] = __floats2half2_rn(v.x, v.y);
    dst[1] = __floats2half2_rn(v.z, v.w);
}
__global__ void mpack_kernel(const int* __restrict__ mask) {
    const size_t nwarps = (size_t)gridDim.x * (blockDim.x >> 5);
    size_t wid = ((size_t)blockIdx.x * blockDim.x + threadIdx.x) >> 5;
    int lane = threadIdx.x & 31;
    for (size_t w = wid; w < (size_t)Bq * Sq * 32; w += nwarps) {
        int v = mask[w * 32 + lane];
        unsigned bits = __ballot_sync(~0u, v != 0);
        if (lane == 0) g_mb[w] = bits;
    }
}

// ============================================================================
// K1: fused QKV projection, fp16 mma + ldmatrix. Q stored pre-scaled by SCL.
// grid (64, NH), 256 thr.
// ============================================================================
__global__ void __launch_bounds__(256) qkv_kernel(
    const float* __restrict__ Wq, const float* __restrict__ bq,
    const float* __restrict__ Wk, const float* __restrict__ bk,
    const float* __restrict__ Wv, const float* __restrict__ bv)
{
    extern __shared__ __half hsm[];
    __half* Hs = hsm;               // 128 x 72
    __half* Ws = hsm + 128 * TS;    // 3 x 64 x 72

    const int tid  = threadIdx.x;
    const int lane = tid & 31;
    const int warp = tid >> 5;
    const int g = lane >> 3, rr = lane & 7;
    const int warpM = warp >> 1;
    const int warpN = warp & 1;
    const int h    = blockIdx.y;
    const int row0 = blockIdx.x * 128;
    const int b    = row0 >> 10;
    const int s    = row0 & 1023;

    for (int i = tid; i < 128 * 8; i += 256) {
        int r = i >> 3, q = i & 7;
        cpa16(sptr(&Hs[r * TS + q * 8]),
              g_Hh + (size_t)(row0 + r) * Dm + h * DH + q * 8);
    }
    CPA_COMMIT();

    const float* Wt[3] = {Wq, Wk, Wv};
    for (int wsel = 0; wsel < 3; wsel++) {
        const float* W = Wt[wsel] + h * DH * DH;
        __half* Wd = Ws + wsel * 64 * TS;
        for (int i = tid; i < 64 * 16; i += 256) {
            int r = i >> 4, q = i & 15;
            float4 v = *(const float4*)&W[r * DH + q * 4];
            __half2* dst = (__half2*)&Wd[r * TS + q * 4];
            dst[0] = __floats2half2_rn(v.x, v.y);
            dst[1] = __floats2half2_rn(v.z, v.w);
        }
    }
    CPA_WAIT(0);
    __syncthreads();

    unsigned a[4][2][4];
    #pragma unroll
    for (int ks = 0; ks < 4; ks++)
        #pragma unroll
        for (int mi = 0; mi < 2; mi++) {
            int row = warpM * 32 + mi * 16 + rr + (g & 1) * 8;
            int col = ks * 16 + (g >> 1) * 8;
            ldm_x4(a[ks][mi], sptr(&Hs[row * TS + col]));
        }

    const float* bt[3] = {bq, bk, bv};
    __half*      Ot[3] = {g_Q, g_K, g_V};

    #pragma unroll
    for (int wsel = 0; wsel < 3; wsel++) {
        const __half* Wd = Ws + wsel * 64 * TS;
        const float scale = (wsel == 0) ? SCL : 1.0f;   // fold score scale into Q
        float c[2][4][4];
        #pragma unroll
        for (int mi = 0; mi < 2; mi++)
            #pragma unroll
            for (int t = 0; t < 4; t++)
                #pragma unroll
                for (int q = 0; q < 4; q++) c[mi][t][q] = 0.f;

        #pragma unroll
        for (int ks = 0; ks < 4; ks++) {
            #pragma unroll
            for (int hn = 0; hn < 2; hn++) {
                int row = warpN * 32 + hn * 16 + rr + (g >> 1) * 8;
                int col = ks * 16 + (g & 1) * 8;
                unsigned bb[4];
                ldm_x4(bb, sptr(&Wd[row * TS + col]));
                #pragma unroll
                for (int mi = 0; mi < 2; mi++) {
                    mma_f16(c[mi][hn * 2 + 0], a[ks][mi], bb[0], bb[1]);
                    mma_f16(c[mi][hn * 2 + 1], a[ks][mi], bb[2], bb[3]);
                }
            }
        }

        const float* bias = bt[wsel] + h * DH;
        __half* O = Ot[wsel] + ((size_t)(b * NH + h) * Sq + s) * DH;
        #pragma unroll
        for (int mi = 0; mi < 2; mi++)
            #pragma unroll
            for (int t = 0; t < 4; t++) {
                int r  = warpM * 32 + mi * 16 + (lane >> 2);
                int cN = warpN * 32 + t * 8 + (lane & 3) * 2;
                float b0v = bias[cN], b1v = bias[cN + 1];
                *(__half2*)&O[(size_t)r * DH + cN] =
                    __floats2half2_rn((c[mi][t][0] + b0v) * scale,
                                      (c[mi][t][1] + b1v) * scale);
                *(__half2*)&O[(size_t)(r + 8) * DH + cN] =
                    __floats2half2_rn((c[mi][t][2] + b0v) * scale,
                                      (c[mi][t][3] + b1v) * scale);
            }
    }
}

// ============================================================================
// K2: attention — fused sweep, e staged in Aout (global, L2-hot), NO psh.
// smem 45KB -> launch_bounds(256,3) -> 24 warps/SM.
// Per 64-key tile: QK^T -> bitmask+ex2 -> e to Aout (f32) + P-frags -> P@V.
// Epilogue: Z reduce, A = e/Z read-modify-write (stcs), cross-warpN O reduce.
// grid (NH, 32, Bq).
// ============================================================================
__global__ void __launch_bounds__(256, 3) attn_kernel(float* __restrict__ Aout)
{
    extern __shared__ __half hsm[];
    __half*   Qs  = hsm;                          // 32 x 72
    __half*   KVs = Qs + 32 * TS;                 // 4 x 64 x 72 (K0,V0,K1,V1)
    unsigned* mb  = (unsigned*)(KVs + 4 * 64 * TS); // 32 x 32 words
    float*    zred = (float*)(mb + 1024);         // 32 x 4

    const int tid = threadIdx.x, lane = tid & 31, warp = tid >> 5;
    const int h = blockIdx.x, b = blockIdx.z, s0 = blockIdx.y * 32;
    const int g = lane >> 3, rr = lane & 7;
    const int warpM = warp >> 2;   // 0..1: 16 query rows
    const int warpN = warp & 3;    // 0..3: 16-key slice within each 64-key tile
    const int rq = lane >> 2, cq = (lane & 3) * 2;

    const __half* Qg = g_Q + ((size_t)(b * NH + h) * Sq + s0) * DH;
    const __half* Kg = g_K + (size_t)(b * NH + h) * Sq * DH;
    const __half* Vg = g_V + (size_t)(b * NH + h) * Sq * DH;
    float* Ab = Aout + (((size_t)h * Bq + b) * Sq + s0) * Sq;   // block A base

    auto issue = [&](int t) {   // K tile t + V tile t into slot pair (t&1)
        __half* dk = KVs + (t & 1) * 2 * (64 * TS);
        __half* dv = dk + 64 * TS;
        const __half* sk = Kg + (size_t)t * 64 * DH;
        const __half* sv = Vg + (size_t)t * 64 * DH;
        for (int i = tid; i < 64 * 8; i += 256) {
            int r = i >> 3, q = i & 7;
            cpa16(sptr(&dk[r * TS + q * 8]), sk + (size_t)r * DH + q * 8);
            cpa16(sptr(&dv[r * TS + q * 8]), sv + (size_t)r * DH + q * 8);
        }
        CPA_COMMIT();
    };

    issue(0);
    for (int i = tid; i < 32 * 8; i += 256) {
        int r = i >> 3, q = i & 7;
        *(uint4*)&Qs[r * TS + q * 8] = ((const uint4*)Qg)[r * 8 + q];
    }
    ((uint4*)mb)[tid] = ((const uint4*)(g_mb + ((size_t)b * Sq + s0) * 32))[tid];
    __syncthreads();

    // Q fragments (loop-invariant)
    unsigned qa[4][4];
    #pragma unroll
    for (int ks = 0; ks < 4; ks++)
        ldm_x4(qa[ks], sptr(&Qs[(warpM * 16 + rr + (g & 1) * 8) * TS +
                                ks * 16 + (g >> 1) * 8]));

    float z0 = 0.f, z1 = 0.f;
    float o[8][4];
    #pragma unroll
    for (int t = 0; t < 8; t++)
        #pragma unroll
        for (int q = 0; q < 4; q++) o[t][q] = 0.f;

    // ---- fused sweep over 16 tiles of 64 keys ----
    #pragma unroll 1
    for (int t = 0; t < 16; t++) {
        CPA_WAIT(0);
        __syncthreads();
        if (t < 15) issue(t + 1);
        const __half* Kt = KVs + (t & 1) * 2 * (64 * TS);
        const __half* Vt = Kt + 64 * TS;

        // scores (pre-scaled by SCL via Q): 16 rows x 16 keys, k=64
        float c[2][4];
        #pragma unroll
        for (int nt = 0; nt < 2; nt++)
            #pragma unroll
            for (int q = 0; q < 4; q++) c[nt][q] = 0.f;
        #pragma unroll
        for (int ks = 0; ks < 4; ks++) {
            unsigned bb[4];
            ldm_x4(bb, sptr(&Kt[(warpN * 16 + rr + (g >> 1) * 8) * TS +
                                ks * 16 + (g & 1) * 8]));
            mma_f16(c[0], qa[ks], bb[0], bb[1]);
            mma_f16(c[1], qa[ks], bb[2], bb[3]);
        }

        // mask + exp (fragment layout) -> e to Aout (f32) + P-frags
        unsigned w0 = mb[(warpM * 16 + rq) * 32 + t * 2 + (warpN >> 1)];
        unsigned w1 = mb[(warpM * 16 + rq + 8) * 32 + t * 2 + (warpN >> 1)];
        unsigned pf[2][2];
        #pragma unroll
        for (int nt = 0; nt < 2; nt++) {
            int bit = (warpN & 1) * 16 + nt * 8 + cq;
            float e00 = (w0 >> bit)       & 1 ? ex2f(c[nt][0]) : 0.f;
            float e01 = (w0 >> (bit + 1)) & 1 ? ex2f(c[nt][1]) : 0.f;
            float e10 = (w1 >> bit)       & 1 ? ex2f(c[nt][2]) : 0.f;
            float e11 = (w1 >> (bit + 1)) & 1 ? ex2f(c[nt][3]) : 0.f;
            z0 += e00 + e01;
            z1 += e10 + e11;
            int cN = t * 64 + warpN * 16 + nt * 8 + cq;
            *(float2*)&Ab[(size_t)(warpM * 16 + rq) * Sq + cN] =
                make_float2(e00, e01);
            *(float2*)&Ab[(size_t)(warpM * 16 + rq + 8) * Sq + cN] =
                make_float2(e10, e11);
            __half2 h0 = __floats2half2_rn(e00, e01);
            __half2 h1 = __floats2half2_rn(e10, e11);
            pf[nt][0] = *(unsigned*)&h0;
            pf[nt][1] = *(unsigned*)&h1;
        }
        unsigned aA[4] = {pf[0][0], pf[0][1], pf[1][0], pf[1][1]};

        // P~ @ V for this tile: k16 x 64 head cols
        #pragma unroll
        for (int vt = 0; vt < 4; vt++) {
            unsigned bb[4];
            ldm_x4_t(bb, sptr(&Vt[(warpN * 16 + rr + (g & 1) * 8) * TS +
                                  vt * 16 + (g >> 1) * 8]));
            mma_f16(o[vt * 2 + 0], aA, bb[0], bb[1]);
            mma_f16(o[vt * 2 + 1], aA, bb[2], bb[3]);
        }
    }
    // Z reduce (quad) before the barrier
    z0 += __shfl_xor_sync(~0u, z0, 1); z0 += __shfl_xor_sync(~0u, z0, 2);
    z1 += __shfl_xor_sync(~0u, z1, 1); z1 += __shfl_xor_sync(~0u, z1, 2);
    if ((lane & 3) == 0) {
        zred[(warpM * 16 + rq) * 4 + warpN]     = z0;
        zred[(warpM * 16 + rq + 8) * 4 + warpN] = z1;
    }
    __syncthreads();   // smem tile reads done; e-writes + zred visible block-wide

    // ---- O partials into freed KV smem ----
    float* red = (float*)KVs;   // [4 warpN][32 rows][stride 66]
    #pragma unroll
    for (int t = 0; t < 8; t++) {
        int col = (t >> 1) * 16 + (t & 1) * 8 + cq;
        red[(warpN * 32 + warpM * 16 + rq) * 66 + col]         = o[t][0];
        red[(warpN * 32 + warpM * 16 + rq) * 66 + col + 1]     = o[t][1];
        red[(warpN * 32 + warpM * 16 + rq + 8) * 66 + col]     = o[t][2];
        red[(warpN * 32 + warpM * 16 + rq + 8) * 66 + col + 1] = o[t][3];
    }

    // ---- A-sweep: A = e * (1/Z), read back (L2-hot) -> stcs ----
    #pragma unroll
    for (int ri = 0; ri < 4; ri++) {
        int rw = warp * 4 + ri;
        float inv = 1.0f / (zred[rw * 4] + zred[rw * 4 + 1] +
                            zred[rw * 4 + 2] + zred[rw * 4 + 3]);
        float4* Ar4 = (float4*)(Ab + (size_t)rw * Sq);
        #pragma unroll
        for (int t = 0; t < 8; t++) {
            float4 e4 = Ar4[t * 32 + lane];
            __stcs(&Ar4[t * 32 + lane],
                   make_float4(e4.x * inv, e4.y * inv, e4.z * inv, e4.w * inv));
        }
    }
    __syncthreads();   // red complete (cross-warp)

    // ---- O final: reduce 4 warpN partials, scale by 1/Z, write heads ----
    {
        int row = tid >> 3, cb = (tid & 7) * 8;
        float inv = 1.0f / (zred[row * 4] + zred[row * 4 + 1] +
                            zred[row * 4 + 2] + zred[row * 4 + 3]);
        float acc[8];
        #pragma unroll
        for (int q = 0; q < 8; q++) acc[q] = 0.f;
        #pragma unroll
        for (int wn = 0; wn < 4; wn++) {
            const float* rp = &red[(wn * 32 + row) * 66 + cb];
            #pragma unroll
            for (int q = 0; q < 8; q++) acc[q] += rp[q];
        }
        __half* Og = g_heads + ((size_t)(b * Sq + s0 + row)) * Dm + h * DH + cb;
        #pragma unroll
        for (int q = 0; q < 4; q++)
            *(__half2*)&Og[q * 2] =
                __floats2half2_rn(acc[q * 2] * inv, acc[q * 2 + 1] * inv);
    }
}

// ============================================================================
// K3: out = heads @ Woh^T + bo. fp16 mma, tile 128x128, cp.async 2-stage,
// single sync per tile. grid (64, 8), 256 thr.
// ============================================================================
__global__ void __launch_bounds__(256) out_kernel(
    const float* __restrict__ bo, float* __restrict__ out)
{
    extern __shared__ __half hsm[];
    __half* As = hsm;                  // 2 x 128 x 72
    __half* Bs = hsm + 2 * 128 * TS;   // 2 x 128 x 72

    const int tid = threadIdx.x, lane = tid & 31, warp = tid >> 5;
    const int g = lane >> 3, rr = lane & 7;
    const int warpM = warp >> 2;
    const int warpN = warp & 3;
    const int r0 = blockIdx.x * 128, n0 = blockIdx.y * 128;

    auto issue = [&](int kt, int buf) {
        __half* ad = As + buf * 128 * TS;
        __half* bd = Bs + buf * 128 * TS;
        const __half* as = g_heads + (size_t)r0 * Dm + kt * 64;
        const __half* bs = g_Woh   + (size_t)n0 * Dm + kt * 64;
        for (int i = tid; i < 128 * 8; i += 256) {
            int r = i >> 3, q = i & 7;
            cpa16(sptr(&ad[r * TS + q * 8]), as + (size_t)r * Dm + q * 8);
        }
        for (int i = tid; i < 128 * 8; i += 256) {
            int r = i >> 3, q = i & 7;
            cpa16(sptr(&bd[r * TS + q * 8]), bs + (size_t)r * Dm + q * 8);
        }
        CPA_COMMIT();
    };

    float c[4][4][4];
    #pragma unroll
    for (int mi = 0; mi < 4; mi++)
        #pragma unroll
        for (int nt = 0; nt < 4; nt++)
            #pragma unroll
            for (int q = 0; q < 4; q++) c[mi][nt][q] = 0.f;

    issue(0, 0);

    for (int kt = 0; kt < 16; kt++) {
        CPA_WAIT(0);
        __syncthreads();
        if (kt < 15) issue(kt + 1, (kt + 1) & 1);
        const __half* At = As + (kt & 1) * 128 * TS;
        const __half* Bt = Bs + (kt & 1) * 128 * TS;

        #pragma unroll
        for (int ks = 0; ks < 4; ks++) {
            int k0 = ks * 16;
            unsigned a[4][4];
            #pragma unroll
            for (int mi = 0; mi < 4; mi++) {
                int row = warpM * 64 + mi * 16 + rr + (g & 1) * 8;
                int col = k0 + (g >> 1) * 8;
                ldm_x4(a[mi], sptr(&At[row * TS + col]));
            }
            unsigned bb[2][4];
            #pragma unroll
            for (int hn = 0; hn < 2; hn++) {
                int row = warpN * 32 + hn * 16 + rr + (g >> 1) * 8;
                int col = k0 + (g & 1) * 8;
                ldm_x4(bb[hn], sptr(&Bt[row * TS + col]));
            }
            #pragma unroll
            for (int mi = 0; mi < 4; mi++) {
                mma_f16(c[mi][0], a[mi], bb[0][0], bb[0][1]);
                mma_f16(c[mi][1], a[mi], bb[0][2], bb[0][3]);
                mma_f16(c[mi][2], a[mi], bb[1][0], bb[1][1]);
                mma_f16(c[mi][3], a[mi], bb[1][2], bb[1][3]);
            }
        }
    }

    #pragma unroll
    for (int mi = 0; mi < 4; mi++) {
        #pragma unroll
        for (int nt = 0; nt < 4; nt++) {
            int r  = r0 + warpM * 64 + mi * 16 + (lane >> 2);
            int cN = n0 + warpN * 32 + nt * 8 + (lane & 3) * 2;
            float b0v = bo[cN], b1v = bo[cN + 1];
            out[(size_t)r * Dm + cN]           = c[mi][nt][0] + b0v;
            out[(size_t)r * Dm + cN + 1]       = c[mi][nt][1] + b1v;
            out[(size_t)(r + 8) * Dm + cN]     = c[mi][nt][2] + b0v;
            out[(size_t)(r + 8) * Dm + cN + 1] = c[mi][nt][3] + b1v;
        }
    }
}

// ============================================================================
extern "C" void kernel_launch(void* const* d_in, const int* in_sizes, int n_in,
                              void* d_out, int out_size)
{
    const float* H    = (const float*)d_in[0];
    const int*   mask = (const int*)  d_in[1];
    const float* Wq   = (const float*)d_in[2];
    const float* bq   = (const float*)d_in[3];
    const float* Wk   = (const float*)d_in[4];
    const float* bk   = (const float*)d_in[5];
    const float* Wv   = (const float*)d_in[6];
    const float* bv   = (const float*)d_in[7];
    const float* Wo   = (const float*)d_in[8];
    const float* bo   = (const float*)d_in[9];

    float* out  = (float*)d_out;
    float* Aout = out + (size_t)Bq * Sq * Dm;

    const int smem1 = (128 * TS + 3 * 64 * TS) * sizeof(__half);            // 46080
    const int smem2 = (32 * TS + 4 * 64 * TS) * sizeof(__half)
                    + 1024 * 4 + 32 * 4 * 4;                                // 46080
    const int smem3 = 4 * 128 * TS * sizeof(__half);                        // 73728

    cudaFuncSetAttribute(qkv_kernel,  cudaFuncAttributeMaxDynamicSharedMemorySize, smem1);
    cudaFuncSetAttribute(attn_kernel, cudaFuncAttributeMaxDynamicSharedMemorySize, smem2);
    cudaFuncSetAttribute(out_kernel,  cudaFuncAttributeMaxDynamicSharedMemorySize, smem3);

    wconv_kernel<<<1024, 256>>>(Wo);
    hconv_kernel<<<8192, 256>>>(H);
    mpack_kernel<<<512, 256>>>(mask);
    qkv_kernel<<<dim3(64, NH), 256, smem1>>>(Wq, bq, Wk, bk, Wv, bv);
    attn_kernel<<<dim3(NH, 32, Bq), 256, smem2>>>(Aout);
    out_kernel<<<dim3(64, 8), 256, smem3>>>(bo, out);
}

// round 17
// speedup vs baseline: 1.1585x; 1.1585x over previous
#include <cuda_runtime.h>
#include <cuda_fp16.h>

#define Bq 8
#define Sq 1024
#define Dm 1024
#define NH 16
#define DH 64

#define PSH 1032   // half score/P row stride (2064B: +4 banks/row, LDSM conflict-free)
#define TS  72     // half tile row stride (144B: +4 banks/row)
#define SCL 0.18033688011112043f  // 0.125 * log2(e)

// ---- scratch (device globals: allocation-free rule) ----
__device__ __half g_Hh[(size_t)Bq*Sq*Dm];
__device__ __half g_Q[(size_t)Bq*NH*Sq*DH];
__device__ __half g_K[(size_t)Bq*NH*Sq*DH];
__device__ __half g_V[(size_t)Bq*NH*Sq*DH];
__device__ __half g_heads[(size_t)Bq*Sq*Dm];
__device__ __half g_Woh[(size_t)Dm*Dm];
__device__ unsigned g_mb[(size_t)Bq*Sq*32];   // bit-packed mask

// ---- helpers ----
__device__ __forceinline__ void mma_f16(float c[4], const unsigned a[4],
                                        unsigned b0, unsigned b1) {
    asm volatile(
        "mma.sync.aligned.m16n8k16.row.col.f32.f16.f16.f32 "
        "{%0,%1,%2,%3}, {%4,%5,%6,%7}, {%8,%9}, {%0,%1,%2,%3};"
        : "+f"(c[0]), "+f"(c[1]), "+f"(c[2]), "+f"(c[3])
        : "r"(a[0]), "r"(a[1]), "r"(a[2]), "r"(a[3]), "r"(b0), "r"(b1));
}
__device__ __forceinline__ unsigned sptr(const void* p) {
    return (unsigned)__cvta_generic_to_shared(p);
}
__device__ __forceinline__ void ldm_x4(unsigned r[4], unsigned addr) {
    asm volatile("ldmatrix.sync.aligned.m8n8.x4.shared.b16 {%0,%1,%2,%3}, [%4];"
                 : "=r"(r[0]), "=r"(r[1]), "=r"(r[2]), "=r"(r[3]) : "r"(addr));
}
__device__ __forceinline__ void ldm_x4_t(unsigned r[4], unsigned addr) {
    asm volatile("ldmatrix.sync.aligned.m8n8.x4.trans.shared.b16 {%0,%1,%2,%3}, [%4];"
                 : "=r"(r[0]), "=r"(r[1]), "=r"(r[2]), "=r"(r[3]) : "r"(addr));
}
__device__ __forceinline__ void cpa16(unsigned dst, const void* src) {
    asm volatile("cp.async.cg.shared.global [%0], [%1], 16;" :: "r"(dst), "l"(src));
}
#define CPA_COMMIT() asm volatile("cp.async.commit_group;")
#define CPA_WAIT(n)  asm volatile("cp.async.wait_group %0;" :: "n"(n))
__device__ __forceinline__ float ex2f(float x) {
    float y;
    asm("ex2.approx.f32 %0, %1;" : "=f"(y) : "f"(x));
    return y;
}

// ============================================================================
// K0a: Wo f32 -> half.  K0b: H f32 -> half.  K0c: mask -> bitpack.
// ============================================================================
__global__ void wconv_kernel(const float* __restrict__ Wo) {
    int i = (blockIdx.x * 256 + threadIdx.x) * 4;
    float4 v = *(const float4*)&Wo[i];
    __half2* dst = (__half2*)&g_Woh[i];
    dst[0] = __floats2half2_rn(v.x, v.y);
    dst[1] = __floats2half2_rn(v.z, v.w);
}
__global__ void hconv_kernel(const float* __restrict__ H) {
    int i = (blockIdx.x * 256 + threadIdx.x) * 4;
    float4 v = *(const float4*)&H[i];
    __half2* dst = (__half2*)&g_Hh[i];
    dst[0] = __floats2half2_rn(v.x, v.y);
    dst[1] = __floats2half2_rn(v.z, v.w);
}
__global__ void mpack_kernel(const int* __restrict__ mask) {
    const size_t nwarps = (size_t)gridDim.x * (blockDim.x >> 5);
    size_t wid = ((size_t)blockIdx.x * blockDim.x + threadIdx.x) >> 5;
    int lane = threadIdx.x & 31;
    for (size_t w = wid; w < (size_t)Bq * Sq * 32; w += nwarps) {
        int v = mask[w * 32 + lane];
        unsigned bits = __ballot_sync(~0u, v != 0);
        if (lane == 0) g_mb[w] = bits;
    }
}

// ============================================================================
// K1: fused QKV projection, fp16 mma + ldmatrix (measured 42us). grid (64, NH).
// ============================================================================
__global__ void __launch_bounds__(256) qkv_kernel(
    const float* __restrict__ Wq, const float* __restrict__ bq,
    const float* __restrict__ Wk, const float* __restrict__ bk,
    const float* __restrict__ Wv, const float* __restrict__ bv)
{
    extern __shared__ __half hsm[];
    __half* Hs = hsm;               // 128 x 72
    __half* Ws = hsm + 128 * TS;    // 3 x 64 x 72

    const int tid  = threadIdx.x;
    const int lane = tid & 31;
    const int warp = tid >> 5;
    const int g = lane >> 3, rr = lane & 7;
    const int warpM = warp >> 1;
    const int warpN = warp & 1;
    const int h    = blockIdx.y;
    const int row0 = blockIdx.x * 128;
    const int b    = row0 >> 10;
    const int s    = row0 & 1023;

    for (int i = tid; i < 128 * 8; i += 256) {
        int r = i >> 3, q = i & 7;
        cpa16(sptr(&Hs[r * TS + q * 8]),
              g_Hh + (size_t)(row0 + r) * Dm + h * DH + q * 8);
    }
    CPA_COMMIT();

    const float* Wt[3] = {Wq, Wk, Wv};
    for (int wsel = 0; wsel < 3; wsel++) {
        const float* W = Wt[wsel] + h * DH * DH;
        __half* Wd = Ws + wsel * 64 * TS;
        for (int i = tid; i < 64 * 16; i += 256) {
            int r = i >> 4, q = i & 15;
            float4 v = *(const float4*)&W[r * DH + q * 4];
            __half2* dst = (__half2*)&Wd[r * TS + q * 4];
            dst[0] = __floats2half2_rn(v.x, v.y);
            dst[1] = __floats2half2_rn(v.z, v.w);
        }
    }
    CPA_WAIT(0);
    __syncthreads();

    unsigned a[4][2][4];
    #pragma unroll
    for (int ks = 0; ks < 4; ks++)
        #pragma unroll
        for (int mi = 0; mi < 2; mi++) {
            int row = warpM * 32 + mi * 16 + rr + (g & 1) * 8;
            int col = ks * 16 + (g >> 1) * 8;
            ldm_x4(a[ks][mi], sptr(&Hs[row * TS + col]));
        }

    const float* bt[3] = {bq, bk, bv};
    __half*      Ot[3] = {g_Q, g_K, g_V};

    #pragma unroll
    for (int wsel = 0; wsel < 3; wsel++) {
        const __half* Wd = Ws + wsel * 64 * TS;
        float c[2][4][4];
        #pragma unroll
        for (int mi = 0; mi < 2; mi++)
            #pragma unroll
            for (int t = 0; t < 4; t++)
                #pragma unroll
                for (int q = 0; q < 4; q++) c[mi][t][q] = 0.f;

        #pragma unroll
        for (int ks = 0; ks < 4; ks++) {
            #pragma unroll
            for (int hn = 0; hn < 2; hn++) {
                int row = warpN * 32 + hn * 16 + rr + (g >> 1) * 8;
                int col = ks * 16 + (g & 1) * 8;
                unsigned bb[4];
                ldm_x4(bb, sptr(&Wd[row * TS + col]));
                #pragma unroll
                for (int mi = 0; mi < 2; mi++) {
                    mma_f16(c[mi][hn * 2 + 0], a[ks][mi], bb[0], bb[1]);
                    mma_f16(c[mi][hn * 2 + 1], a[ks][mi], bb[2], bb[3]);
                }
            }
        }

        const float* bias = bt[wsel] + h * DH;
        __half* O = Ot[wsel] + ((size_t)(b * NH + h) * Sq + s) * DH;
        #pragma unroll
        for (int mi = 0; mi < 2; mi++)
            #pragma unroll
            for (int t = 0; t < 4; t++) {
                int r  = warpM * 32 + mi * 16 + (lane >> 2);
                int cN = warpN * 32 + t * 8 + (lane & 3) * 2;
                float b0v = bias[cN], b1v = bias[cN + 1];
                *(__half2*)&O[(size_t)r * DH + cN] =
                    __floats2half2_rn(c[mi][t][0] + b0v, c[mi][t][1] + b1v);
                *(__half2*)&O[(size_t)(r + 8) * DH + cN] =
                    __floats2half2_rn(c[mi][t][2] + b0v, c[mi][t][3] + b1v);
            }
    }
}

// ============================================================================
// K2: attention — fused sweep (R15, measured ~268us). 32 query rows, 256 thr.
// Per 64-key tile: QK^T mma -> bitmask+ex2 -> e to psh + P-frags (C->A id)
// -> P@V mma. Z in regs. Epilogue: Z reduce, A = e/Z sweep, cross-warpN O
// reduce via freed KV smem. grid (NH, 32, Bq), launch_bounds(256,2).
// ============================================================================
__global__ void __launch_bounds__(256, 2) attn_kernel(float* __restrict__ Aout)
{
    extern __shared__ __half hsm[];
    __half*   psh = hsm;                          // 32 x 1032: e values
    __half*   Qs  = psh + 32 * PSH;               // 32 x 72
    __half*   KVs = Qs + 32 * TS;                 // 4 x 64 x 72 (K0,V0,K1,V1)
    unsigned* mb  = (unsigned*)(KVs + 4 * 64 * TS); // 32 x 32 words
    float*    zred = (float*)(mb + 1024);         // 32 x 4

    const int tid = threadIdx.x, lane = tid & 31, warp = tid >> 5;
    const int h = blockIdx.x, b = blockIdx.z, s0 = blockIdx.y * 32;
    const int g = lane >> 3, rr = lane & 7;
    const int warpM = warp >> 2;   // 0..1: 16 query rows
    const int warpN = warp & 3;    // 0..3: 16-key slice within each 64-key tile
    const int rq = lane >> 2, cq = (lane & 3) * 2;

    const __half* Qg = g_Q + ((size_t)(b * NH + h) * Sq + s0) * DH;
    const __half* Kg = g_K + (size_t)(b * NH + h) * Sq * DH;
    const __half* Vg = g_V + (size_t)(b * NH + h) * Sq * DH;

    auto issue = [&](int t) {   // K tile t + V tile t into slot pair (t&1)
        __half* dk = KVs + (t & 1) * 2 * (64 * TS);
        __half* dv = dk + 64 * TS;
        const __half* sk = Kg + (size_t)t * 64 * DH;
        const __half* sv = Vg + (size_t)t * 64 * DH;
        for (int i = tid; i < 64 * 8; i += 256) {
            int r = i >> 3, q = i & 7;
            cpa16(sptr(&dk[r * TS + q * 8]), sk + (size_t)r * DH + q * 8);
            cpa16(sptr(&dv[r * TS + q * 8]), sv + (size_t)r * DH + q * 8);
        }
        CPA_COMMIT();
    };

    issue(0);
    // Q tile 32x64 + mask bits (32 rows x 32 words = 4KB)
    for (int i = tid; i < 32 * 8; i += 256) {
        int r = i >> 3, q = i & 7;
        *(uint4*)&Qs[r * TS + q * 8] = ((const uint4*)Qg)[r * 8 + q];
    }
    ((uint4*)mb)[tid] = ((const uint4*)(g_mb + ((size_t)b * Sq + s0) * 32))[tid];
    __syncthreads();

    // Q fragments (loop-invariant): rows warpM*16..+16, k 0..64
    unsigned qa[4][4];
    #pragma unroll
    for (int ks = 0; ks < 4; ks++)
        ldm_x4(qa[ks], sptr(&Qs[(warpM * 16 + rr + (g & 1) * 8) * TS +
                                ks * 16 + (g >> 1) * 8]));

    float z0 = 0.f, z1 = 0.f;
    float o[8][4];
    #pragma unroll
    for (int t = 0; t < 8; t++)
        #pragma unroll
        for (int q = 0; q < 4; q++) o[t][q] = 0.f;

    // ---- fused sweep over 16 tiles of 64 keys ----
    #pragma unroll 1
    for (int t = 0; t < 16; t++) {
        CPA_WAIT(0);
        __syncthreads();
        if (t < 15) issue(t + 1);
        const __half* Kt = KVs + (t & 1) * 2 * (64 * TS);
        const __half* Vt = Kt + 64 * TS;

        // scores: 16 rows x 16 keys (warp slice), k=64
        float c[2][4];
        #pragma unroll
        for (int nt = 0; nt < 2; nt++)
            #pragma unroll
            for (int q = 0; q < 4; q++) c[nt][q] = 0.f;
        #pragma unroll
        for (int ks = 0; ks < 4; ks++) {
            unsigned bb[4];
            ldm_x4(bb, sptr(&Kt[(warpN * 16 + rr + (g >> 1) * 8) * TS +
                                ks * 16 + (g & 1) * 8]));
            mma_f16(c[0], qa[ks], bb[0], bb[1]);
            mma_f16(c[1], qa[ks], bb[2], bb[3]);
        }

        // mask + exp (fragment layout, bitmask) + psh store + P-frags
        unsigned w0 = mb[(warpM * 16 + rq) * 32 + t * 2 + (warpN >> 1)];
        unsigned w1 = mb[(warpM * 16 + rq + 8) * 32 + t * 2 + (warpN >> 1)];
        unsigned pf[2][2];
        #pragma unroll
        for (int nt = 0; nt < 2; nt++) {
            int bit = (warpN & 1) * 16 + nt * 8 + cq;
            float e00 = (w0 >> bit)       & 1 ? ex2f(c[nt][0] * SCL) : 0.f;
            float e01 = (w0 >> (bit + 1)) & 1 ? ex2f(c[nt][1] * SCL) : 0.f;
            float e10 = (w1 >> bit)       & 1 ? ex2f(c[nt][2] * SCL) : 0.f;
            float e11 = (w1 >> (bit + 1)) & 1 ? ex2f(c[nt][3] * SCL) : 0.f;
            z0 += e00 + e01;
            z1 += e10 + e11;
            __half2 h0 = __floats2half2_rn(e00, e01);
            __half2 h1 = __floats2half2_rn(e10, e11);
            int cN = t * 64 + warpN * 16 + nt * 8 + cq;
            *(__half2*)&psh[(warpM * 16 + rq) * PSH + cN]     = h0;
            *(__half2*)&psh[(warpM * 16 + rq + 8) * PSH + cN] = h1;
            pf[nt][0] = *(unsigned*)&h0;
            pf[nt][1] = *(unsigned*)&h1;
        }
        unsigned aA[4] = {pf[0][0], pf[0][1], pf[1][0], pf[1][1]};

        // P~ @ V for this tile: k16 (warp's 16 keys) x 64 head cols
        #pragma unroll
        for (int vt = 0; vt < 4; vt++) {
            unsigned bb[4];
            ldm_x4_t(bb, sptr(&Vt[(warpN * 16 + rr + (g & 1) * 8) * TS +
                                  vt * 16 + (g >> 1) * 8]));
            mma_f16(o[vt * 2 + 0], aA, bb[0], bb[1]);
            mma_f16(o[vt * 2 + 1], aA, bb[2], bb[3]);
        }
    }
    __syncthreads();   // all smem tile reads done; psh complete (cross-warp)

    // ---- Z reduce (quad -> zred) + O partials into freed KV smem ----
    z0 += __shfl_xor_sync(~0u, z0, 1); z0 += __shfl_xor_sync(~0u, z0, 2);
    z1 += __shfl_xor_sync(~0u, z1, 1); z1 += __shfl_xor_sync(~0u, z1, 2);
    if ((lane & 3) == 0) {
        zred[(warpM * 16 + rq) * 4 + warpN]     = z0;
        zred[(warpM * 16 + rq + 8) * 4 + warpN] = z1;
    }
    float* red = (float*)KVs;   // [4 warpN][32 rows][stride 66]
    #pragma unroll
    for (int t = 0; t < 8; t++) {
        int col = (t >> 1) * 16 + (t & 1) * 8 + cq;
        red[(warpN * 32 + warpM * 16 + rq) * 66 + col]         = o[t][0];
        red[(warpN * 32 + warpM * 16 + rq) * 66 + col + 1]     = o[t][1];
        red[(warpN * 32 + warpM * 16 + rq + 8) * 66 + col]     = o[t][2];
        red[(warpN * 32 + warpM * 16 + rq + 8) * 66 + col + 1] = o[t][3];
    }
    __syncthreads();

    // ---- A-sweep: A = e * (1/Z), vectorized, streaming ----
    #pragma unroll
    for (int ri = 0; ri < 4; ri++) {
        int rw = warp * 4 + ri;
        float inv = 1.0f / (zred[rw * 4] + zred[rw * 4 + 1] +
                            zred[rw * 4 + 2] + zred[rw * 4 + 3]);
        float4* Ar4 = (float4*)(Aout + (((size_t)h * Bq + b) * Sq + s0 + rw) * Sq);
        #pragma unroll
        for (int t = 0; t < 8; t++) {
            int j = t * 128 + lane * 4;
            uint2 pp = *(uint2*)&psh[rw * PSH + j];
            __half2 p01 = *(__half2*)&pp.x, p23 = *(__half2*)&pp.y;
            __stcs(&Ar4[t * 32 + lane],
                   make_float4(__low2float(p01) * inv, __high2float(p01) * inv,
                               __low2float(p23) * inv, __high2float(p23) * inv));
        }
    }

    // ---- O final: reduce 4 warpN partials, scale by 1/Z, write heads ----
    {
        int row = tid >> 3, cb = (tid & 7) * 8;
        float inv = 1.0f / (zred[row * 4] + zred[row * 4 + 1] +
                            zred[row * 4 + 2] + zred[row * 4 + 3]);
        float acc[8];
        #pragma unroll
        for (int q = 0; q < 8; q++) acc[q] = 0.f;
        #pragma unroll
        for (int wn = 0; wn < 4; wn++) {
            const float* rp = &red[(wn * 32 + row) * 66 + cb];
            #pragma unroll
            for (int q = 0; q < 8; q++) acc[q] += rp[q];
        }
        __half* Og = g_heads + ((size_t)(b * Sq + s0 + row)) * Dm + h * DH + cb;
        #pragma unroll
        for (int q = 0; q < 4; q++)
            *(__half2*)&Og[q * 2] =
                __floats2half2_rn(acc[q * 2] * inv, acc[q * 2 + 1] * inv);
    }
}

// ============================================================================
// K3: out = heads @ Woh^T + bo. fp16 mma, tile 128x128, cp.async 2-stage,
// single sync per tile, launch_bounds(256,2) -> 2 CTAs/SM. grid (64, 8).
// ============================================================================
__global__ void __launch_bounds__(256, 2) out_kernel(
    const float* __restrict__ bo, float* __restrict__ out)
{
    extern __shared__ __half hsm[];
    __half* As = hsm;                  // 2 x 128 x 72
    __half* Bs = hsm + 2 * 128 * TS;   // 2 x 128 x 72

    const int tid = threadIdx.x, lane = tid & 31, warp = tid >> 5;
    const int g = lane >> 3, rr = lane & 7;
    const int warpM = warp >> 2;
    const int warpN = warp & 3;
    const int r0 = blockIdx.x * 128, n0 = blockIdx.y * 128;

    auto issue = [&](int kt, int buf) {
        __half* ad = As + buf * 128 * TS;
        __half* bd = Bs + buf * 128 * TS;
        const __half* as = g_heads + (size_t)r0 * Dm + kt * 64;
        const __half* bs = g_Woh   + (size_t)n0 * Dm + kt * 64;
        for (int i = tid; i < 128 * 8; i += 256) {
            int r = i >> 3, q = i & 7;
            cpa16(sptr(&ad[r * TS + q * 8]), as + (size_t)r * Dm + q * 8);
        }
        for (int i = tid; i < 128 * 8; i += 256) {
            int r = i >> 3, q = i & 7;
            cpa16(sptr(&bd[r * TS + q * 8]), bs + (size_t)r * Dm + q * 8);
        }
        CPA_COMMIT();
    };

    float c[4][4][4];
    #pragma unroll
    for (int mi = 0; mi < 4; mi++)
        #pragma unroll
        for (int nt = 0; nt < 4; nt++)
            #pragma unroll
            for (int q = 0; q < 4; q++) c[mi][nt][q] = 0.f;

    issue(0, 0);

    for (int kt = 0; kt < 16; kt++) {
        CPA_WAIT(0);
        __syncthreads();
        if (kt < 15) issue(kt + 1, (kt + 1) & 1);
        const __half* At = As + (kt & 1) * 128 * TS;
        const __half* Bt = Bs + (kt & 1) * 128 * TS;

        #pragma unroll
        for (int ks = 0; ks < 4; ks++) {
            int k0 = ks * 16;
            unsigned a[4][4];
            #pragma unroll
            for (int mi = 0; mi < 4; mi++) {
                int row = warpM * 64 + mi * 16 + rr + (g & 1) * 8;
                int col = k0 + (g >> 1) * 8;
                ldm_x4(a[mi], sptr(&At[row * TS + col]));
            }
            unsigned bb[2][4];
            #pragma unroll
            for (int hn = 0; hn < 2; hn++) {
                int row = warpN * 32 + hn * 16 + rr + (g >> 1) * 8;
                int col = k0 + (g & 1) * 8;
                ldm_x4(bb[hn], sptr(&Bt[row * TS + col]));
            }
            #pragma unroll
            for (int mi = 0; mi < 4; mi++) {
                mma_f16(c[mi][0], a[mi], bb[0][0], bb[0][1]);
                mma_f16(c[mi][1], a[mi], bb[0][2], bb[0][3]);
                mma_f16(c[mi][2], a[mi], bb[1][0], bb[1][1]);
                mma_f16(c[mi][3], a[mi], bb[1][2], bb[1][3]);
            }
        }
    }

    #pragma unroll
    for (int mi = 0; mi < 4; mi++) {
        #pragma unroll
        for (int nt = 0; nt < 4; nt++) {
            int r  = r0 + warpM * 64 + mi * 16 + (lane >> 2);
            int cN = n0 + warpN * 32 + nt * 8 + (lane & 3) * 2;
            float b0v = bo[cN], b1v = bo[cN + 1];
            out[(size_t)r * Dm + cN]           = c[mi][nt][0] + b0v;
            out[(size_t)r * Dm + cN + 1]       = c[mi][nt][1] + b1v;
            out[(size_t)(r + 8) * Dm + cN]     = c[mi][nt][2] + b0v;
            out[(size_t)(r + 8) * Dm + cN + 1] = c[mi][nt][3] + b1v;
        }
    }
}

// ============================================================================
extern "C" void kernel_launch(void* const* d_in, const int* in_sizes, int n_in,
                              void* d_out, int out_size)
{
    const float* H    = (const float*)d_in[0];
    const int*   mask = (const int*)  d_in[1];
    const float* Wq   = (const float*)d_in[2];
    const float* bq   = (const float*)d_in[3];
    const float* Wk   = (const float*)d_in[4];
    const float* bk   = (const float*)d_in[5];
    const float* Wv   = (const float*)d_in[6];
    const float* bv   = (const float*)d_in[7];
    const float* Wo   = (const float*)d_in[8];
    const float* bo   = (const float*)d_in[9];

    float* out  = (float*)d_out;
    float* Aout = out + (size_t)Bq * Sq * Dm;

    const int smem1 = (128 * TS + 3 * 64 * TS) * sizeof(__half);            // 46080
    const int smem2 = (32 * PSH + 32 * TS + 4 * 64 * TS) * sizeof(__half)
                    + 1024 * 4 + 32 * 4 * 4;                                // 112128
    const int smem3 = 4 * 128 * TS * sizeof(__half);                        // 73728

    cudaFuncSetAttribute(qkv_kernel,  cudaFuncAttributeMaxDynamicSharedMemorySize, smem1);
    cudaFuncSetAttribute(attn_kernel, cudaFuncAttributeMaxDynamicSharedMemorySize, smem2);
    cudaFuncSetAttribute(out_kernel,  cudaFuncAttributeMaxDynamicSharedMemorySize, smem3);

    wconv_kernel<<<1024, 256>>>(Wo);
    hconv_kernel<<<8192, 256>>>(H);
    mpack_kernel<<<512, 256>>>(mask);
    qkv_kernel<<<dim3(64, NH), 256, smem1>>>(Wq, bq, Wk, bk, Wv, bv);
    attn_kernel<<<dim3(NH, 32, Bq), 256, smem2>>>(Aout);
    out_kernel<<<dim3(64, 8), 256, smem3>>>(bo, out);
}